// round 15
// baseline (speedup 1.0000x reference)
#include <cuda_runtime.h>
#include <math.h>
#include <stdint.h>

#define B_IMG   32
#define NBOX    50
#define NCLS    20
#define A_TOT   10647
#define NUM_NEG 1000
#define EPSF    1e-7f
#define FOURPI2 0.4052847345693511f   // 4/pi^2
#define HALF_A  5376                  // 21*256 ; thread covers a and a+HALF_A
#define KEY_BLOCKS 21
#define NT      256

// ---- scratch (no allocations allowed) ----
__device__ float    g_pos[B_IMG];
__device__ float    g_neg[B_IMG];
__device__ uint32_t g_keys[B_IMG * A_TOT];
__device__ float    g_cf[B_IMG * A_TOT];      // focal0(conf) per anchor
__device__ int      g_done[B_IMG];            // per-image arrival counters
__device__ int      g_cnt = 0;                // cross-image counter

__constant__ float c_asc[9][2] = {
    {10.f/416.f,13.f/416.f},{16.f/416.f,30.f/416.f},{33.f/416.f,23.f/416.f},
    {30.f/416.f,61.f/416.f},{62.f/416.f,45.f/416.f},{59.f/416.f,119.f/416.f},
    {116.f/416.f,90.f/416.f},{156.f/416.f,198.f/416.f},{373.f/416.f,326.f/416.f}};
__constant__ float c_fs9[9] = {52.f,52.f,52.f,26.f,26.f,26.f,13.f,13.f,13.f};

// ---- precise math helpers (value-bearing paths) ----
__device__ __forceinline__ float softplusf(float x) {
    return fmaxf(x, 0.f) + log1pf(expf(-fabsf(x)));
}
__device__ __forceinline__ float sigm(float x) { return 1.f / (1.f + expf(-x)); }
__device__ __forceinline__ float focal0(float x) {           // focal(x, t=0)
    float pr = sigm(x);
    return softplusf(x) * 0.75f * pr * pr;
}
__device__ __forceinline__ float focal1(float x) {           // focal(x, t=1)
    float pr = sigm(x); float q = 1.f - pr;
    return softplusf(-x) * 0.25f * q * q;
}
__device__ __forceinline__ float bce01(float x, bool t1) {
    return t1 ? softplusf(-x) : softplusf(x);
}

// Full-precision CIoU on two ltrb boxes (matches reference formula)
__device__ __forceinline__ float ciouf(float l1, float t1, float r1, float b1,
                                       float l2, float t2, float r2, float b2) {
    float iw = fminf(r1, r2) - fmaxf(l1, l2); iw = fmaxf(iw, 0.f);
    float ih = fminf(b1, b2) - fmaxf(t1, t2); ih = fmaxf(ih, 0.f);
    float inter = iw * ih;
    float w1 = r1 - l1, h1 = b1 - t1;
    float w2 = r2 - l2, h2 = b2 - t2;
    float uni = w1 * h1 + w2 * h2 - inter + EPSF;
    float iou = inter / uni;
    float cw = fmaxf(r1, r2) - fminf(l1, l2);
    float ch = fmaxf(b1, b2) - fminf(t1, t2);
    float c2 = cw * cw + ch * ch + EPSF;
    float dx = (l1 + r1) - (l2 + r2);
    float dy = (t1 + b1) - (t2 + b2);
    float rho2 = 0.25f * (dx * dx + dy * dy);
    float dv = atanf(w1 / (h1 + EPSF)) - atanf(w2 / (h2 + EPSF));
    float v = FOURPI2 * dv * dv;
    float al = v / (1.0f - iou + v + EPSF);
    return iou - rho2 / c2 - al * v;
}

// ---- fast CIoU chain state for the OHEM key path (ordering only) ----
struct AncBox {
    float l, t, r, b, px, py, pw, ph, area, atanv, mx;
};

__device__ __forceinline__ void anc_decode(AncBox& s, const float* __restrict__ p,
                                           const float* __restrict__ ancs,
                                           int b, int a)
{
    const float* pp = p + ((size_t)b * A_TOT + a) * 25;
    const int level = (a < 8112) ? 0 : ((a < 10140) ? 1 : 2);
    const float rfa = (level == 0) ? (1.f/52.f) : ((level == 1) ? (1.f/26.f) : (1.f/13.f));
    const float4 anc = __ldg((const float4*)(ancs) + a);
    float sx = __fdividef(1.f, 1.f + __expf(-pp[0]));
    float sy = __fdividef(1.f, 1.f + __expf(-pp[1]));
    s.px = sx * rfa + anc.x;
    s.py = sy * rfa + anc.y;
    s.pw = __expf(pp[2]) * anc.z;
    s.ph = __expf(pp[3]) * anc.w;
    s.l = s.px - s.pw * 0.5f; s.t = s.py - s.ph * 0.5f;
    s.r = s.px + s.pw * 0.5f; s.b = s.py + s.ph * 0.5f;
    s.area = s.pw * s.ph;
    s.atanv = atanf(__fdividef(s.pw, s.ph + EPSF));
    s.mx = -1e30f;
}

// one fast CIoU step vs box j (bx = ltrb, ex = {cx, cy, area+eps, atan}, wh = {w,h})
__device__ __forceinline__ void anc_step(AncBox& s, float4 bx, float4 ex, float2 wh)
{
    float iwu = fminf(s.r, bx.z) - fmaxf(s.l, bx.x);
    float ihu = fminf(s.b, bx.w) - fmaxf(s.t, bx.y);
    float inter = fmaxf(iwu, 0.f) * fmaxf(ihu, 0.f);
    float uni = s.area + ex.z - inter;                 // ex.z = area2+eps
    float iou = __fdividef(inter, uni);
    float cw = (s.pw + wh.x) - iwu;                    // max-min identity
    float ch = (s.ph + wh.y) - ihu;
    float c2 = fmaf(cw, cw, fmaf(ch, ch, EPSF));
    float dx = s.px - ex.x, dy = s.py - ex.y;          // centers -> 0.25 folded
    float rho2 = fmaf(dx, dx, dy * dy);
    float dv = ex.w - s.atanv;
    float v = FOURPI2 * (dv * dv);
    float ci = iou - __fdividef(rho2, c2)
                   - __fdividef(v * v, 1.f - iou + v + EPSF);
    s.mx = fmaxf(s.mx, ci);
}

__device__ __forceinline__ uint32_t key_of(float mx)
{
    float masked = (mx < 0.5f) ? mx : __int_as_float(0x7f800000); // +inf
    uint32_t u = __float_as_uint(masked);
    return (u & 0x80000000u) ? ~u : (u | 0x80000000u);
}

// ---- warp-aggregated histogram add (ALL 32 lanes must reach the call) ----
__device__ __forceinline__ void hist_add(unsigned int* hist, bool pred, uint32_t bin)
{
    unsigned active = __ballot_sync(0xffffffffu, pred);
    if (pred) {
        unsigned peers = __match_any_sync(active, bin);
        int leader = __ffs(peers) - 1;
        if ((int)(threadIdx.x & 31) == leader)
            atomicAdd(&hist[bin], (unsigned)__popc(peers));
    }
}

// =====================================================================
// ONE fused kernel, NO dynamic smem (the R14 version reserved 42.6KB
// per block for the selector and choked key-phase occupancy to 3
// blocks/SM). Selector reads g_keys straight from global: 42.6KB/image
// is L1-resident after the first sweep (L1=228KB, persists within the
// launch), and the selector is off the critical path anyway (overlaps
// other images' key generation).
//
// Grid (21, 32) x 256 threads.
//  every block:   OHEM keys (2 chains/thread) + focal0 values
//  block x==0:    + anchor matching + positive losses
//  LAST-ARRIVING block per image: radix-selects that image's 1000
//  smallest keys (per-image atomic counter; no spinning). The global
//  last selector folds the final scalar.
// =====================================================================
#define EQ_CAP 64
__global__ void __launch_bounds__(NT)
k_fused(const float* __restrict__ p, const float* __restrict__ boxes,
        const int* __restrict__ labels, const float* __restrict__ ancs,
        float* __restrict__ out)
{
    const int b = blockIdx.y;
    const int tid = threadIdx.x, wid = tid >> 5, lane = tid & 31;

    __shared__ float4 sA[NBOX];             // l,t,r,b
    __shared__ float4 sB[NBOX];             // cx, cy, area+eps, atan(w/h)
    __shared__ float2 sC[NBOX];             // w, h
    __shared__ float  wsum[8];
    __shared__ unsigned int hist[256];
    __shared__ unsigned int wscan[8];
    __shared__ uint32_t s_prefix;
    __shared__ int s_k;
    __shared__ int eqIdx[EQ_CAP];
    __shared__ int eqCnt;
    __shared__ float red[8];
    __shared__ int s_sel, s_last;

    if (tid < NBOX) {
        const float* bp = boxes + (size_t)(b * NBOX + tid) * 4;
        float l = bp[0], t = bp[1], r = bp[2], bb = bp[3];
        float w = r - l, h = bb - t;
        sA[tid] = make_float4(l, t, r, bb);
        sB[tid] = make_float4((l + r) * 0.5f, (t + bb) * 0.5f,
                              w * h + EPSF,
                              atanf(w / (h + EPSF)));
        sC[tid] = make_float2(w, h);
    }
    __syncthreads();

    // ---------------- per-anchor keys: 2 chains per thread -------------------
    {
        const int a0 = blockIdx.x * NT + tid;        // [0, HALF_A) always valid
        const int a1 = a0 + HALF_A;
        const bool do1 = (a1 < A_TOT);
        AncBox s0, s1;
        anc_decode(s0, p, ancs, b, a0);
        anc_decode(s1, p, ancs, b, do1 ? a1 : 0);

        #pragma unroll 5
        for (int j = 0; j < NBOX; j++) {
            float4 bx = sA[j];
            float4 ex = sB[j];
            float2 wh = sC[j];
            anc_step(s0, bx, ex, wh);
            anc_step(s1, bx, ex, wh);
        }
        g_keys[b * A_TOT + a0] = key_of(s0.mx);
        g_cf[b * A_TOT + a0] = focal0(p[((size_t)b * A_TOT + a0) * 25 + 4]);
        if (do1) {
            g_keys[b * A_TOT + a1] = key_of(s1.mx);
            g_cf[b * A_TOT + a1] = focal0(p[((size_t)b * A_TOT + a1) * 25 + 4]);
        }
    }

    // ---------------- matching + positive losses (block x == 0 only) ---------
    if (blockIdx.x == 0) {
        const float* pb = p + (size_t)b * A_TOT * 25;
        float wacc = 0.f;

        for (int i = wid; i < NBOX; i += 8) {
            const float4 bx = sA[i];
            const float l1 = bx.x, t1 = bx.y, r1 = bx.z, bb1 = bx.w;

            float best = -1e30f; int bestm = 1 << 30;
            if (lane < 9) {
                const int m = lane;
                float fs = c_fs9[m];
                float ax = floorf((l1 + r1) * 0.5f * fs) / fs;
                float ay = floorf((t1 + bb1) * 0.5f * fs) / fs;
                float aw = c_asc[m][0], ah = c_asc[m][1];
                best = ciouf(l1, t1, r1, bb1,
                             ax - aw * 0.5f, ay - ah * 0.5f,
                             ax + aw * 0.5f, ay + ah * 0.5f);
                bestm = m;
            }
            for (int o = 8; o > 0; o >>= 1) {
                float v2 = __shfl_down_sync(0xffffffffu, best, o);
                int   m2 = __shfl_down_sync(0xffffffffu, bestm, o);
                if (v2 > best || (v2 == best && m2 < bestm)) { best = v2; bestm = m2; }
            }
            const int k = __shfl_sync(0xffffffffu, bestm, 0);

            const int level = k / 3;
            const float fs = c_fs9[k];
            const int col = (int)floorf((l1 + r1) * 0.5f * fs);
            const int row = (int)floorf((t1 + bb1) * 0.5f * fs);
            const int fsl = (level == 0) ? 52 : ((level == 1) ? 26 : 13);
            const int cum = (level == 0) ? 0 : ((level == 1) ? 2704 : 3380);
            // NOTE: reference adds +level (not k%3) — replicate exactly.
            const int midx = (cum + row * fsl + col) * 3 + level;
            const float* pm = pb + (size_t)midx * 25;

            float contrib = 0.f;
            if (lane < NCLS) {
                contrib = bce01(pm[5 + lane], (labels[b * NBOX + i] - 1) == lane);
            } else if (lane == NCLS) {
                contrib = focal1(pm[4]);
            } else if (lane == NCLS + 1) {
                float fa = (float)fsl;
                float acx = ancs[midx * 4 + 0], acy = ancs[midx * 4 + 1];
                float aw  = ancs[midx * 4 + 2], ah  = ancs[midx * 4 + 3];
                float px = sigm(pm[0]) / fa + acx;
                float py = sigm(pm[1]) / fa + acy;
                float pw = expf(pm[2]) * aw;
                float ph = expf(pm[3]) * ah;
                float iou1 = ciouf(l1, t1, r1, bb1,
                                   px - pw * 0.5f, py - ph * 0.5f,
                                   px + pw * 0.5f, py + ph * 0.5f);
                float gw = r1 - l1, gh = bb1 - t1;
                contrib = (2.f - gw * gh) * (1.f - iou1);
            }
            for (int o = 16; o > 0; o >>= 1)
                contrib += __shfl_down_sync(0xffffffffu, contrib, o);
            if (lane == 0) wacc += contrib;
        }
        if (lane == 0) wsum[wid] = wacc;
        __syncthreads();
        if (tid == 0) {
            float s = 0.f;
            for (int w = 0; w < 8; w++) s += wsum[w];
            g_pos[b] = s;   // l_cls + l_iou + l_conf_pos (undivided)
        }
    }

    // ---------------- arrive: last block of this image becomes selector ------
    __threadfence();          // release this thread's global writes
    __syncthreads();          // all threads' fences done
    if (tid == 0) {
        int t = atomicAdd(&g_done[b], 1);
        s_sel = (t == KEY_BLOCKS - 1);
        if (s_sel) g_done[b] = 0;      // self-reset (we are last; safe)
        eqCnt = 0;
    }
    __syncthreads();
    if (!s_sel) return;
    __threadfence();          // acquire: make peers' key writes visible

    // =============== selector: radix-select 1000 smallest keys ===============
    // keys read straight from global; 42.6KB becomes L1-resident.
    const uint32_t* __restrict__ kb = g_keys + b * A_TOT;
    if (tid == 0) { s_prefix = 0u; s_k = NUM_NEG; }

    for (int pass = 0; pass < 4; pass++) {
        const int shift = 24 - 8 * pass;
        const uint32_t himask = (pass == 0) ? 0u : (0xFFFFFFFFu << (shift + 8));
        hist[tid] = 0u;
        __syncthreads();
        const uint32_t pref = s_prefix;
        const unsigned kcur = (unsigned)s_k;
        // thread-independent base -> uniform trip count -> safe ballots
        for (int base = 0; base < A_TOT; base += NT) {
            const int i = base + tid;
            bool valid = (i < A_TOT);
            uint32_t key = valid ? kb[i] : 0u;
            bool pred = valid && ((key & himask) == pref);
            hist_add(hist, pred, (key >> shift) & 255u);
        }
        __syncthreads();
        // parallel 256-bin prefix scan (8 warps) + one-hot digit pick
        unsigned orig = hist[tid], v = orig;
        #pragma unroll
        for (int o = 1; o < 32; o <<= 1) {
            unsigned n = __shfl_up_sync(0xffffffffu, v, o);
            if (lane >= o) v += n;
        }
        if (lane == 31) wscan[wid] = v;
        __syncthreads();
        {
            unsigned off = 0;
            for (int w = 0; w < wid; w++) off += wscan[w];
            unsigned incl = v + off;
            unsigned excl = incl - orig;
            if (orig > 0u && excl < kcur && kcur <= incl) {
                s_prefix = pref | ((uint32_t)tid << shift);
                s_k = (int)(kcur - excl);
            }
        }
        __syncthreads();
    }
    const uint32_t V = s_prefix;
    const int kRem = s_k;

    // ties: collect indices of keys == V (rank among equals = index order)
    for (int i = tid; i < A_TOT; i += NT) {
        if (kb[i] == V) {
            int pos = atomicAdd(&eqCnt, 1);
            if (pos < EQ_CAP) eqIdx[pos] = i;
        }
    }
    __syncthreads();
    const int nEq = eqCnt;

    float part = 0.f;
    for (int i = tid; i < A_TOT; i += NT) {
        uint32_t key = kb[i];
        bool take = false;
        if (key < V) take = true;
        else if (key == V) {
            int rank = 0;
            if (nEq <= EQ_CAP) {
                for (int e = 0; e < nEq; e++) rank += (eqIdx[e] < i);
            } else {
                // pathological mass-tie fallback: exact O(i) scan
                for (int j = 0; j < i; j++) rank += (kb[j] == V);
            }
            take = (rank < kRem);
        }
        if (take) part += g_cf[b * A_TOT + i];
    }
    for (int o = 16; o > 0; o >>= 1)
        part += __shfl_down_sync(0xffffffffu, part, o);
    if (lane == 0) red[wid] = part;
    __syncthreads();
    if (tid == 0) {
        float s = 0.f;
        for (int w = 0; w < 8; w++) s += red[w];
        g_neg[b] = s;
        __threadfence();
        int t = atomicAdd(&g_cnt, 1);
        s_last = (t == B_IMG - 1);
    }
    __syncthreads();
    if (s_last && tid == 0) {
        __threadfence();
        float s = 0.f;
        for (int bb = 0; bb < B_IMG; bb++)
            s += g_pos[bb] * (1.f / (float)NBOX) + g_neg[bb];
        out[0] = s * (1.f / (float)B_IMG);
        g_cnt = 0;   // self-reset for deterministic graph replays
    }
}

extern "C" void kernel_launch(void* const* d_in, const int* in_sizes, int n_in,
                              void* d_out, int out_size)
{
    const float* p      = (const float*)d_in[0];   // [32,10647,25]
    const float* boxes  = (const float*)d_in[1];   // [32,50,4] ltrb
    const int*   labels = (const int*)d_in[2];     // [32,50]
    const float* ancs   = (const float*)d_in[3];   // [10647,4] xywh
    float* out = (float*)d_out;

    dim3 g1(KEY_BLOCKS, B_IMG);
    k_fused<<<g1, NT>>>(p, boxes, labels, ancs, out);
}

// round 16
// speedup vs baseline: 1.5176x; 1.5176x over previous
#include <cuda_runtime.h>
#include <math.h>
#include <stdint.h>

#define B_IMG   32
#define NBOX    50
#define NCLS    20
#define A_TOT   10647
#define NUM_NEG 1000
#define EPSF    1e-7f
#define FOURPI2 0.4052847345693511f   // 4/pi^2
#define HALF_A  5376                  // 21*256 ; thread covers a and a+HALF_A
#define KEY_BLOCKS 21

// ---- scratch (no allocations allowed) ----
__device__ float    g_pos[B_IMG];
__device__ float    g_neg[B_IMG];
__device__ uint32_t g_keys[B_IMG * A_TOT];
__device__ int      g_cnt = 0;        // last-block counter (self-resetting)

__constant__ float c_asc[9][2] = {
    {10.f/416.f,13.f/416.f},{16.f/416.f,30.f/416.f},{33.f/416.f,23.f/416.f},
    {30.f/416.f,61.f/416.f},{62.f/416.f,45.f/416.f},{59.f/416.f,119.f/416.f},
    {116.f/416.f,90.f/416.f},{156.f/416.f,198.f/416.f},{373.f/416.f,326.f/416.f}};
__constant__ float c_fs9[9] = {52.f,52.f,52.f,26.f,26.f,26.f,13.f,13.f,13.f};

// ---- precise math helpers (value-bearing paths) ----
__device__ __forceinline__ float softplusf(float x) {
    return fmaxf(x, 0.f) + log1pf(expf(-fabsf(x)));
}
__device__ __forceinline__ float sigm(float x) { return 1.f / (1.f + expf(-x)); }
__device__ __forceinline__ float focal0(float x) {           // focal(x, t=0)
    float pr = sigm(x);
    return softplusf(x) * 0.75f * pr * pr;
}
__device__ __forceinline__ float focal1(float x) {           // focal(x, t=1)
    float pr = sigm(x); float q = 1.f - pr;
    return softplusf(-x) * 0.25f * q * q;
}
__device__ __forceinline__ float bce01(float x, bool t1) {
    return t1 ? softplusf(-x) : softplusf(x);
}

// Full-precision CIoU on two ltrb boxes (matches reference formula)
__device__ __forceinline__ float ciouf(float l1, float t1, float r1, float b1,
                                       float l2, float t2, float r2, float b2) {
    float iw = fminf(r1, r2) - fmaxf(l1, l2); iw = fmaxf(iw, 0.f);
    float ih = fminf(b1, b2) - fmaxf(t1, t2); ih = fmaxf(ih, 0.f);
    float inter = iw * ih;
    float w1 = r1 - l1, h1 = b1 - t1;
    float w2 = r2 - l2, h2 = b2 - t2;
    float uni = w1 * h1 + w2 * h2 - inter + EPSF;
    float iou = inter / uni;
    float cw = fmaxf(r1, r2) - fminf(l1, l2);
    float ch = fmaxf(b1, b2) - fminf(t1, t2);
    float c2 = cw * cw + ch * ch + EPSF;
    float dx = (l1 + r1) - (l2 + r2);
    float dy = (t1 + b1) - (t2 + b2);
    float rho2 = 0.25f * (dx * dx + dy * dy);
    float dv = atanf(w1 / (h1 + EPSF)) - atanf(w2 / (h2 + EPSF));
    float v = FOURPI2 * dv * dv;
    float al = v / (1.f - iou + v + EPSF);
    return iou - rho2 / c2 - al * v;
}

// ---- fast CIoU chain state for the OHEM key path (ordering only) ----
struct AncBox {
    float l, t, r, b, px, py, pw, ph, area, atanv, mx;
};

__device__ __forceinline__ void anc_decode(AncBox& s, const float* __restrict__ p,
                                           const float* __restrict__ ancs,
                                           int b, int a)
{
    const float* pp = p + ((size_t)b * A_TOT + a) * 25;
    const int level = (a < 8112) ? 0 : ((a < 10140) ? 1 : 2);
    const float rfa = (level == 0) ? (1.f/52.f) : ((level == 1) ? (1.f/26.f) : (1.f/13.f));
    const float4 anc = __ldg((const float4*)(ancs) + a);
    float sx = __fdividef(1.f, 1.f + __expf(-pp[0]));
    float sy = __fdividef(1.f, 1.f + __expf(-pp[1]));
    s.px = sx * rfa + anc.x;
    s.py = sy * rfa + anc.y;
    s.pw = __expf(pp[2]) * anc.z;
    s.ph = __expf(pp[3]) * anc.w;
    s.l = s.px - s.pw * 0.5f; s.t = s.py - s.ph * 0.5f;
    s.r = s.px + s.pw * 0.5f; s.b = s.py + s.ph * 0.5f;
    s.area = s.pw * s.ph;
    s.atanv = atanf(__fdividef(s.pw, s.ph + EPSF));
    s.mx = -1e30f;
}

// one fast CIoU step vs box j (bx = ltrb, ex = {cx, cy, area+eps, atan}, wh = {w,h})
__device__ __forceinline__ void anc_step(AncBox& s, float4 bx, float4 ex, float2 wh)
{
    float iwu = fminf(s.r, bx.z) - fmaxf(s.l, bx.x);
    float ihu = fminf(s.b, bx.w) - fmaxf(s.t, bx.y);
    float inter = fmaxf(iwu, 0.f) * fmaxf(ihu, 0.f);
    float uni = s.area + ex.z - inter;                 // ex.z = area2+eps
    float iou = __fdividef(inter, uni);
    float cw = (s.pw + wh.x) - iwu;                    // max-min identity
    float ch = (s.ph + wh.y) - ihu;
    float c2 = fmaf(cw, cw, fmaf(ch, ch, EPSF));
    float dx = s.px - ex.x, dy = s.py - ex.y;          // centers -> 0.25 folded
    float rho2 = fmaf(dx, dx, dy * dy);
    float dv = ex.w - s.atanv;
    float v = FOURPI2 * (dv * dv);
    float ci = iou - __fdividef(rho2, c2)
                   - __fdividef(v * v, 1.f - iou + v + EPSF);
    s.mx = fmaxf(s.mx, ci);
}

__device__ __forceinline__ uint32_t key_of(float mx)
{
    float masked = (mx < 0.5f) ? mx : __int_as_float(0x7f800000); // +inf
    uint32_t u = __float_as_uint(masked);
    return (u & 0x80000000u) ? ~u : (u | 0x80000000u);
}

// =====================================================================
// Kernel 1 (R9-measured, byte-identical): per-anchor OHEM keys (2
// chains per thread); block x==0 of each image also does anchor
// matching + positive losses.
//
// Matching note: the reference's +ids offset trick guarantees each box's
// argmax over the nb*9 candidate matrix falls within its OWN 9
// candidates, and CIoU is translation-invariant -> argmax over the 9
// own-cell candidates (lowest index on ties) equals the reference.
// =====================================================================
__global__ void __launch_bounds__(256)
k_keys_match(const float* __restrict__ p, const float* __restrict__ boxes,
             const int* __restrict__ labels, const float* __restrict__ ancs)
{
    const int b = blockIdx.y;
    const int tid = threadIdx.x, wid = tid >> 5, lane = tid & 31;

    __shared__ float4 sA[NBOX];   // l,t,r,b
    __shared__ float4 sB[NBOX];   // cx, cy, area+eps, atan(w/h)
    __shared__ float2 sC[NBOX];   // w, h
    __shared__ float  wsum[8];
    if (tid < NBOX) {
        const float* bp = boxes + (size_t)(b * NBOX + tid) * 4;
        float l = bp[0], t = bp[1], r = bp[2], bb = bp[3];
        float w = r - l, h = bb - t;
        sA[tid] = make_float4(l, t, r, bb);
        sB[tid] = make_float4((l + r) * 0.5f, (t + bb) * 0.5f,
                              w * h + EPSF,
                              atanf(w / (h + EPSF)));
        sC[tid] = make_float2(w, h);
    }
    __syncthreads();

    // ---------------- per-anchor keys: 2 chains per thread -------------------
    {
        const int a0 = blockIdx.x * 256 + tid;       // [0, HALF_A)
        const int a1 = a0 + HALF_A;                  // [HALF_A, 2*HALF_A)
        const bool do1 = (a1 < A_TOT);
        AncBox s0, s1;
        anc_decode(s0, p, ancs, b, a0);
        anc_decode(s1, p, ancs, b, do1 ? a1 : 0);

        #pragma unroll 5
        for (int j = 0; j < NBOX; j++) {
            float4 bx = sA[j];
            float4 ex = sB[j];
            float2 wh = sC[j];
            anc_step(s0, bx, ex, wh);
            anc_step(s1, bx, ex, wh);
        }
        g_keys[b * A_TOT + a0] = key_of(s0.mx);
        if (do1) g_keys[b * A_TOT + a1] = key_of(s1.mx);
    }

    // ---------------- matching + positive losses (block x == 0 only) ---------
    if (blockIdx.x != 0) return;
    const float* pb = p + (size_t)b * A_TOT * 25;
    float wacc = 0.f;

    for (int i = wid; i < NBOX; i += 8) {
        const float4 bx = sA[i];
        const float l1 = bx.x, t1 = bx.y, r1 = bx.z, bb1 = bx.w;

        // lanes 0..8 each evaluate one of the 9 own-cell candidates (precise)
        float best = -1e30f; int bestm = 1 << 30;
        if (lane < 9) {
            const int m = lane;
            float fs = c_fs9[m];
            float ax = floorf((l1 + r1) * 0.5f * fs) / fs;
            float ay = floorf((t1 + bb1) * 0.5f * fs) / fs;
            float aw = c_asc[m][0], ah = c_asc[m][1];
            best = ciouf(l1, t1, r1, bb1,
                         ax - aw * 0.5f, ay - ah * 0.5f,
                         ax + aw * 0.5f, ay + ah * 0.5f);
            bestm = m;
        }
        for (int o = 8; o > 0; o >>= 1) {
            float v2 = __shfl_down_sync(0xffffffffu, best, o);
            int   m2 = __shfl_down_sync(0xffffffffu, bestm, o);
            if (v2 > best || (v2 == best && m2 < bestm)) { best = v2; bestm = m2; }
        }
        const int k = __shfl_sync(0xffffffffu, bestm, 0);

        const int level = k / 3;
        const float fs = c_fs9[k];
        const int col = (int)floorf((l1 + r1) * 0.5f * fs);
        const int row = (int)floorf((t1 + bb1) * 0.5f * fs);
        const int fsl = (level == 0) ? 52 : ((level == 1) ? 26 : 13);
        const int cum = (level == 0) ? 0 : ((level == 1) ? 2704 : 3380);
        // NOTE: reference adds +level (not k%3) — replicate exactly.
        const int midx = (cum + row * fsl + col) * 3 + level;
        const float* pm = pb + (size_t)midx * 25;

        float contrib = 0.f;
        if (lane < NCLS) {
            contrib = bce01(pm[5 + lane], (labels[b * NBOX + i] - 1) == lane);
        } else if (lane == NCLS) {
            contrib = focal1(pm[4]);
        } else if (lane == NCLS + 1) {
            float fa = (float)fsl;
            float acx = ancs[midx * 4 + 0], acy = ancs[midx * 4 + 1];
            float aw  = ancs[midx * 4 + 2], ah  = ancs[midx * 4 + 3];
            float px = sigm(pm[0]) / fa + acx;
            float py = sigm(pm[1]) / fa + acy;
            float pw = expf(pm[2]) * aw;
            float ph = expf(pm[3]) * ah;
            float iou1 = ciouf(l1, t1, r1, bb1,
                               px - pw * 0.5f, py - ph * 0.5f,
                               px + pw * 0.5f, py + ph * 0.5f);
            float gw = r1 - l1, gh = bb1 - t1;
            contrib = (2.f - gw * gh) * (1.f - iou1);
        }
        for (int o = 16; o > 0; o >>= 1)
            contrib += __shfl_down_sync(0xffffffffu, contrib, o);
        if (lane == 0) wacc += contrib;
    }
    if (lane == 0) wsum[wid] = wacc;
    __syncthreads();
    if (tid == 0) {
        float s = 0.f;
        for (int w = 0; w < 8; w++) s += wsum[w];
        g_pos[b] = s;   // l_cls + l_iou + l_conf_pos (undivided)
    }
}

// =====================================================================
// Kernel 2: per-image radix-select of the 1000 smallest keys (exact
// top_k tie semantics) + sum focal(conf,0); last block folds the final
// scalar. R9 structure (measured best: naive smem atomics, 1024
// threads) MINUS the smem key staging: all passes read g_keys from
// global — 42.6KB/image is L1-resident after the first pass (L1=228KB,
// persists within the launch), and dropping the staging removes an
// 11-iteration copy sweep + a barrier and lets pass 1 overlap the
// initial DRAM fetch.
// Smem: 1024 (hist) + 32 (wscan) + 256 (eqIdx) + 128 (red) + scalars.
// =====================================================================
#define EQ_CAP 64
#define SEL_NT 1024
__global__ void __launch_bounds__(SEL_NT)
k_select_neg(const float* __restrict__ p, float* __restrict__ out)
{
    const int b = blockIdx.x;
    const uint32_t* __restrict__ kb = g_keys + b * A_TOT;
    __shared__ unsigned int hist[256];
    __shared__ unsigned int wscan[8];
    __shared__ uint32_t s_prefix;
    __shared__ int s_k;
    __shared__ int eqIdx[EQ_CAP];
    __shared__ int eqCnt;
    __shared__ float red[32];
    __shared__ int s_last;

    const int tid = threadIdx.x;
    const int warp = tid >> 5, lane = tid & 31;
    if (tid == 0) { s_prefix = 0u; s_k = NUM_NEG; eqCnt = 0; }
    __syncthreads();

    for (int pass = 0; pass < 4; pass++) {
        const int shift = 24 - 8 * pass;
        const uint32_t himask = (pass == 0) ? 0u : (0xFFFFFFFFu << (shift + 8));
        if (tid < 256) hist[tid] = 0u;
        __syncthreads();
        const uint32_t pref = s_prefix;
        const unsigned kcur = (unsigned)s_k;
        for (int i = tid; i < A_TOT; i += SEL_NT) {
            uint32_t key = kb[i];
            if ((key & himask) == pref)
                atomicAdd(&hist[(key >> shift) & 255u], 1u);
        }
        __syncthreads();
        // parallel 256-bin prefix scan (8 warps) + one-hot digit pick
        unsigned v = 0, orig = 0;
        if (tid < 256) {
            orig = hist[tid]; v = orig;
            #pragma unroll
            for (int o = 1; o < 32; o <<= 1) {
                unsigned n = __shfl_up_sync(0xffffffffu, v, o);
                if (lane >= o) v += n;
            }
            if (lane == 31) wscan[warp] = v;
        }
        __syncthreads();
        if (tid < 256) {
            unsigned off = 0;
            for (int w = 0; w < warp; w++) off += wscan[w];
            unsigned incl = v + off;
            unsigned excl = incl - orig;
            if (orig > 0u && excl < kcur && kcur <= incl) {
                s_prefix = pref | ((uint32_t)tid << shift);
                s_k = (int)(kcur - excl);
            }
        }
        __syncthreads();
    }
    const uint32_t V = s_prefix;
    const int kRem = s_k;

    // collect indices of keys == V (rank among equals follows index order)
    for (int i = tid; i < A_TOT; i += SEL_NT) {
        if (kb[i] == V) {
            int pos = atomicAdd(&eqCnt, 1);
            if (pos < EQ_CAP) eqIdx[pos] = i;
        }
    }
    __syncthreads();
    const int nEq = eqCnt;

    float part = 0.f;
    for (int i = tid; i < A_TOT; i += SEL_NT) {
        uint32_t key = kb[i];
        bool take = false;
        if (key < V) take = true;
        else if (key == V) {
            int rank = 0;
            if (nEq <= EQ_CAP) {
                for (int e = 0; e < nEq; e++) rank += (eqIdx[e] < i);
            } else {
                // pathological mass-tie fallback: exact O(i) scan
                for (int j = 0; j < i; j++) rank += (kb[j] == V);
            }
            take = (rank < kRem);
        }
        if (take) part += focal0(p[((size_t)b * A_TOT + i) * 25 + 4]);
    }
    for (int o = 16; o > 0; o >>= 1)
        part += __shfl_down_sync(0xffffffffu, part, o);
    if (lane == 0) red[warp] = part;
    __syncthreads();
    if (tid == 0) {
        float s = 0.f;
        for (int w = 0; w < 32; w++) s += red[w];
        g_neg[b] = s;
        __threadfence();
        int t = atomicAdd(&g_cnt, 1);
        s_last = (t == B_IMG - 1);
    }
    __syncthreads();
    if (s_last && tid == 0) {
        __threadfence();
        float s = 0.f;
        for (int bb = 0; bb < B_IMG; bb++)
            s += g_pos[bb] * (1.f / (float)NBOX) + g_neg[bb];
        out[0] = s * (1.f / (float)B_IMG);
        g_cnt = 0;   // self-reset for deterministic graph replays
    }
}

extern "C" void kernel_launch(void* const* d_in, const int* in_sizes, int n_in,
                              void* d_out, int out_size)
{
    const float* p      = (const float*)d_in[0];   // [32,10647,25]
    const float* boxes  = (const float*)d_in[1];   // [32,50,4] ltrb
    const int*   labels = (const int*)d_in[2];     // [32,50]
    const float* ancs   = (const float*)d_in[3];   // [10647,4] xywh
    float* out = (float*)d_out;

    dim3 g1(KEY_BLOCKS, B_IMG);
    k_keys_match<<<g1, 256>>>(p, boxes, labels, ancs);

    k_select_neg<<<B_IMG, SEL_NT>>>(p, out);
}